// round 1
// baseline (speedup 1.0000x reference)
#include <cuda_runtime.h>
#include <math.h>

// Problem constants
#define BATCH   128
#define CHAN    3
#define HW      224
#define PATCH   16
#define NPD     14                  // patches per spatial dim
#define NPATCH  (NPD*NPD)           // 196
#define M_DIM   (BATCH*NPATCH)      // 25088
#define K_DIM   (CHAN*PATCH*PATCH)  // 768
#define N_DIM   768
#define IMG_STRIDE (CHAN*HW*HW)     // 150528
#define CH_STRIDE  (HW*HW)          // 50176

#define PI_D 3.141592653589793238462643383279502884

// Scratch: DCT-transformed weights, layout wt[k][n], k = c*256 + i*16 + j, n = out-channel
__device__ float g_wt[K_DIM * N_DIM];

// ---------------------------------------------------------------------------
// Kernel 1: fold the per-8x8 DCT into the conv weights.
//   For each 8x8 sub-block W of the 16x16 kernel:  w' = D^T W D
//   (because <D X D^T, W> = <X, D^T W D> with orthonormal D)
// One block per (out_channel o, in_channel c); 256 threads = one (i,j) each.
// ---------------------------------------------------------------------------
__global__ void dct_weight_kernel(const float* __restrict__ w) {
    __shared__ float Ws[16][16];
    __shared__ float Ds[8][8];

    int o = blockIdx.x / CHAN;
    int c = blockIdx.x % CHAN;
    int tid = threadIdx.x;

    if (tid < 64) {
        int k = tid >> 3, n = tid & 7;
        double v = sqrt(2.0 / 8.0) * cos(PI_D * (2.0 * n + 1.0) * k / 16.0);
        if (k == 0) v *= (1.0 / sqrt(2.0));
        Ds[k][n] = (float)v;
    }
    Ws[tid >> 4][tid & 15] = w[(o * CHAN + c) * 256 + tid];
    __syncthreads();

    int i = tid >> 4, j = tid & 15;
    int bi = i & 8, bj = j & 8;     // which 8x8 sub-block
    int ii = i & 7, jj = j & 7;     // index inside sub-block

    float s = 0.0f;
    #pragma unroll
    for (int u = 0; u < 8; u++) {
        float du = Ds[u][ii];
        #pragma unroll
        for (int v = 0; v < 8; v++)
            s += du * Ws[bi + u][bj + v] * Ds[v][jj];
    }

    int k = c * 256 + i * 16 + j;
    g_wt[k * N_DIM + o] = s;
}

// ---------------------------------------------------------------------------
// Kernel 2: patch-embed GEMM on the RAW input (DCT already folded into w').
//   out[m][n] = sum_k x_patch[m][k] * wt[k][n] + bias[n]
//   m = b*196 + ph*14 + pw ; k = c*256 + i*16 + j
// 128x128x16 tile, 256 threads, 8x8 per-thread micro-tile,
// register-prefetch double buffering.
// ---------------------------------------------------------------------------
#define BM 128
#define BN 128
#define BK 16
#define TM 8
#define TN 8
#define AS_STRIDE 132   // padded; 132 floats = 528B, 16B-aligned rows

__global__ __launch_bounds__(256, 2)
void gemm_kernel(const float* __restrict__ x, const float* __restrict__ bias,
                 float* __restrict__ out) {
    __shared__ float As[BK][AS_STRIDE];   // transposed: As[k_local][m_local]
    __shared__ float Bs[BK][BN];

    const int tid = threadIdx.x;
    const int m0 = blockIdx.y * BM;
    const int n0 = blockIdx.x * BN;

    // ---- A-tile load mapping: 512 float4 per tile, 2 per thread ----
    // float4 index f covers (row = f/4, j4 = (f%4)*4); f = tid and tid+256.
    const int ar = tid >> 2;          // row 0..63 (second row = 64+ar)
    const int ac = (tid & 3) * 4;     // j offset within patch row: 0,4,8,12
    long baseA0, baseA1;
    {
        int m = m0 + ar;
        int b = m / NPATCH, pr = m % NPATCH;
        baseA0 = (long)b * IMG_STRIDE + (long)(pr / NPD) * (PATCH * HW) + (pr % NPD) * PATCH;
        m = m0 + 64 + ar;
        b = m / NPATCH; pr = m % NPATCH;
        baseA1 = (long)b * IMG_STRIDE + (long)(pr / NPD) * (PATCH * HW) + (pr % NPD) * PATCH;
    }

    // ---- B-tile load mapping: rows of wt are contiguous (coalesced) ----
    const int bkr = tid >> 5;          // k_local 0..7 (second = +8)
    const int bnc = (tid & 31) * 4;    // n offset 0..124

    const int trow = (tid >> 4) * TM;
    const int tcol = (tid & 15) * TN;

    float acc[TM][TN];
    #pragma unroll
    for (int i = 0; i < TM; i++)
        #pragma unroll
        for (int j = 0; j < TN; j++) acc[i][j] = 0.0f;

    float4 pa0, pa1, pb0, pb1;

    // prefetch tile 0 (k0 = 0 -> c = 0, i = 0)
    pa0 = *(const float4*)(x + baseA0 + ac);
    pa1 = *(const float4*)(x + baseA1 + ac);
    pb0 = *(const float4*)(g_wt + (long)bkr * N_DIM + n0 + bnc);
    pb1 = *(const float4*)(g_wt + (long)(bkr + 8) * N_DIM + n0 + bnc);

    const int NT = K_DIM / BK;   // 48
    for (int t = 0; t < NT; t++) {
        // store prefetched tile to shared
        As[ac + 0][ar] = pa0.x;  As[ac + 1][ar] = pa0.y;
        As[ac + 2][ar] = pa0.z;  As[ac + 3][ar] = pa0.w;
        As[ac + 0][64 + ar] = pa1.x;  As[ac + 1][64 + ar] = pa1.y;
        As[ac + 2][64 + ar] = pa1.z;  As[ac + 3][64 + ar] = pa1.w;
        *(float4*)&Bs[bkr][bnc]     = pb0;
        *(float4*)&Bs[bkr + 8][bnc] = pb1;
        __syncthreads();

        if (t + 1 < NT) {
            const int k0 = (t + 1) * BK;
            const int c  = k0 >> 8;            // k0 / 256
            const int i  = (k0 & 255) >> 4;    // row inside patch
            const long off = (long)c * CH_STRIDE + (long)i * HW + ac;
            pa0 = *(const float4*)(x + baseA0 + off);
            pa1 = *(const float4*)(x + baseA1 + off);
            pb0 = *(const float4*)(g_wt + (long)(k0 + bkr) * N_DIM + n0 + bnc);
            pb1 = *(const float4*)(g_wt + (long)(k0 + bkr + 8) * N_DIM + n0 + bnc);
        }

        #pragma unroll
        for (int kk = 0; kk < BK; kk++) {
            float4 a0 = *(float4*)&As[kk][trow];
            float4 a1 = *(float4*)&As[kk][trow + 4];
            float4 b0 = *(float4*)&Bs[kk][tcol];
            float4 b1 = *(float4*)&Bs[kk][tcol + 4];
            float a[TM] = {a0.x, a0.y, a0.z, a0.w, a1.x, a1.y, a1.z, a1.w};
            float b[TN] = {b0.x, b0.y, b0.z, b0.w, b1.x, b1.y, b1.z, b1.w};
            #pragma unroll
            for (int i = 0; i < TM; i++)
                #pragma unroll
                for (int j = 0; j < TN; j++)
                    acc[i][j] += a[i] * b[j];
        }
        __syncthreads();
    }

    // epilogue: add bias, write out (out layout == [B, 196, 768] row-major)
    float bb[TN];
    #pragma unroll
    for (int j = 0; j < TN; j++) bb[j] = bias[n0 + tcol + j];

    #pragma unroll
    for (int r = 0; r < TM; r++) {
        long row = (long)(m0 + trow + r) * N_DIM + n0 + tcol;
        float4 o0, o1;
        o0.x = acc[r][0] + bb[0]; o0.y = acc[r][1] + bb[1];
        o0.z = acc[r][2] + bb[2]; o0.w = acc[r][3] + bb[3];
        o1.x = acc[r][4] + bb[4]; o1.y = acc[r][5] + bb[5];
        o1.z = acc[r][6] + bb[6]; o1.w = acc[r][7] + bb[7];
        *(float4*)(out + row)     = o0;
        *(float4*)(out + row + 4) = o1;
    }
}

// ---------------------------------------------------------------------------
extern "C" void kernel_launch(void* const* d_in, const int* in_sizes, int n_in,
                              void* d_out, int out_size) {
    const float* x = (const float*)d_in[0];   // [128,3,224,224]
    const float* w = (const float*)d_in[1];   // [768,3,16,16]
    const float* b = (const float*)d_in[2];   // [768]
    float* out = (float*)d_out;               // [128,196,768]

    dct_weight_kernel<<<N_DIM * CHAN, 256>>>(w);
    gemm_kernel<<<dim3(N_DIM / BN, M_DIM / BM), 256>>>(x, b, out);
}

// round 2
// speedup vs baseline: 2.3876x; 2.3876x over previous
#include <cuda_runtime.h>
#include <math.h>

// Problem constants
#define BATCH   128
#define CHAN    3
#define HW      224
#define PATCH   16
#define NPD     14
#define NPATCH  (NPD*NPD)           // 196
#define M_DIM   (BATCH*NPATCH)      // 25088
#define K_DIM   (CHAN*PATCH*PATCH)  // 768
#define N_DIM   768
#define IMG_STRIDE (CHAN*HW*HW)     // 150528
#define CH_STRIDE  (HW*HW)          // 50176

#define PI_D 3.141592653589793238462643383279502884

// DCT-folded weights: wt[k][n], k = c*256 + i*16 + j
__device__ float g_wt[K_DIM * N_DIM];

// ---------------------------------------------------------------------------
// Kernel 1: fold per-8x8 DCT into conv weights:  w' = D^T W D per sub-block.
// ---------------------------------------------------------------------------
__global__ void dct_weight_kernel(const float* __restrict__ w) {
    __shared__ float Ws[16][16];
    __shared__ float Ds[8][8];

    int o = blockIdx.x / CHAN;
    int c = blockIdx.x % CHAN;
    int tid = threadIdx.x;

    if (tid < 64) {
        int k = tid >> 3, n = tid & 7;
        double v = sqrt(2.0 / 8.0) * cos(PI_D * (2.0 * n + 1.0) * k / 16.0);
        if (k == 0) v *= (1.0 / sqrt(2.0));
        Ds[k][n] = (float)v;
    }
    Ws[tid >> 4][tid & 15] = w[(o * CHAN + c) * 256 + tid];
    __syncthreads();

    int i = tid >> 4, j = tid & 15;
    int bi = i & 8, bj = j & 8;
    int ii = i & 7, jj = j & 7;

    float s = 0.0f;
    #pragma unroll
    for (int u = 0; u < 8; u++) {
        float du = Ds[u][ii];
        #pragma unroll
        for (int v = 0; v < 8; v++)
            s += du * Ws[bi + u][bj + v] * Ds[v][jj];
    }
    g_wt[(c * 256 + i * 16 + j) * N_DIM + o] = s;
}

// ---------------------------------------------------------------------------
// Kernel 2: TF32 tensor-core GEMM with 4-stage cp.async pipeline.
//   BM=128 BN=128 BK=32, 8 warps (4m x 2n), warp tile 32x64,
//   mma.sync.m16n8k8.tf32 (2 m-tiles x 8 n-tiles x 4 k-steps per BK).
// ---------------------------------------------------------------------------
#define BM 128
#define BN 128
#define BK 32
#define STAGES 4
#define NT (K_DIM / BK)     // 24
#define AS_LD 36            // A row stride (floats): 36 % 32 banks -> conflict-free frag loads
#define BS_LD 136           // B row stride: 136 % 32 = 8 -> conflict-free frag loads
#define ASZ (BM * AS_LD)    // 4608 floats
#define BSZ (BK * BS_LD)    // 4352 floats
#define STG_STRIDE (ASZ + BSZ)   // 8960 floats
#define SMEM_BYTES (STAGES * STG_STRIDE * 4)  // 143360 B

__device__ __forceinline__ unsigned cvt_tf32(float f) {
    unsigned r;
    asm("cvt.rna.tf32.f32 %0, %1;" : "=r"(r) : "f"(f));
    return r;
}

__device__ __forceinline__ void mma_tf32(float* c, const unsigned* a, const unsigned* b) {
    asm volatile(
        "mma.sync.aligned.m16n8k8.row.col.f32.tf32.tf32.f32 "
        "{%0,%1,%2,%3}, {%4,%5,%6,%7}, {%8,%9}, {%0,%1,%2,%3};"
        : "+f"(c[0]), "+f"(c[1]), "+f"(c[2]), "+f"(c[3])
        : "r"(a[0]), "r"(a[1]), "r"(a[2]), "r"(a[3]), "r"(b[0]), "r"(b[1]));
}

__global__ __launch_bounds__(256)
void gemm_tf32_kernel(const float* __restrict__ x,
                      const float* __restrict__ bias,
                      float* __restrict__ out) {
    extern __shared__ float smem[];
    const int tid  = threadIdx.x;
    const int lane = tid & 31, wid = tid >> 5;
    const int warp_m = wid >> 1, warp_n = wid & 1;
    const int g = lane >> 2, tig = lane & 3;

    const int m0 = blockIdx.y * BM;
    const int n0 = blockIdx.x * BN;

    // ---- A global-load mapping: 1024 float4/tile, 4 per thread ----
    const int kq   = tid & 7;         // which float4 within the 32-wide k chunk
    const int kq4  = kq >> 2;         // extra patch-row (k 16..31)
    const int jof  = (kq & 3) * 4;    // column offset inside patch row
    const int mloc0 = tid >> 3;       // 0..31; rows mloc0 + 32*s
    long abase[4];
    #pragma unroll
    for (int s = 0; s < 4; s++) {
        int m = m0 + mloc0 + 32 * s;
        int b = m / NPATCH, pr = m % NPATCH;
        abase[s] = (long)b * IMG_STRIDE + (long)(pr / NPD) * (PATCH * HW)
                 + (long)(pr % NPD) * PATCH;
    }
    // ---- B global-load mapping: 1024 float4/tile, 4 per thread ----
    const int nq    = tid & 31;       // float4 column
    const int kloc0 = tid >> 5;       // rows kloc0 + 8*s

    float acc[2][8][4];
    #pragma unroll
    for (int i = 0; i < 2; i++)
        #pragma unroll
        for (int j = 0; j < 8; j++)
            #pragma unroll
            for (int p = 0; p < 4; p++) acc[i][j][p] = 0.0f;

    // tile loader (cp.async, 16B each)
    auto load_tile = [&](int t, int st) {
        float* As = smem + st * STG_STRIDE;
        float* Bs = As + ASZ;
        const int k0 = t * BK;
        const int c  = k0 >> 8;
        const int i0 = (k0 & 255) >> 4;
        const long aoff = (long)c * CH_STRIDE + (long)(i0 + kq4) * HW + jof;
        #pragma unroll
        for (int s = 0; s < 4; s++) {
            unsigned sa = (unsigned)__cvta_generic_to_shared(
                &As[(mloc0 + 32 * s) * AS_LD + kq * 4]);
            const float* gp = x + abase[s] + aoff;
            asm volatile("cp.async.cg.shared.global [%0], [%1], 16;\n"
                         :: "r"(sa), "l"(gp));
        }
        #pragma unroll
        for (int s = 0; s < 4; s++) {
            int k = kloc0 + 8 * s;
            unsigned sb = (unsigned)__cvta_generic_to_shared(
                &Bs[k * BS_LD + nq * 4]);
            const float* gp = g_wt + (long)(k0 + k) * N_DIM + n0 + nq * 4;
            asm volatile("cp.async.cg.shared.global [%0], [%1], 16;\n"
                         :: "r"(sb), "l"(gp));
        }
    };

    // prologue: fill STAGES-1 stages
    #pragma unroll
    for (int s = 0; s < STAGES - 1; s++) {
        load_tile(s, s);
        asm volatile("cp.async.commit_group;\n");
    }

    for (int t = 0; t < NT; t++) {
        asm volatile("cp.async.wait_group %0;\n" :: "n"(STAGES - 2));
        __syncthreads();

        const int tn = t + STAGES - 1;
        if (tn < NT) load_tile(tn, tn % STAGES);
        asm volatile("cp.async.commit_group;\n");

        const float* As = smem + (t % STAGES) * STG_STRIDE;
        const float* Bs = As + ASZ;

        #pragma unroll
        for (int kk = 0; kk < 4; kk++) {
            unsigned afr[2][4];
            #pragma unroll
            for (int mt = 0; mt < 2; mt++) {
                const int rb = warp_m * 32 + mt * 16;
                afr[mt][0] = cvt_tf32(As[(rb + g) * AS_LD + kk * 8 + tig]);
                afr[mt][1] = cvt_tf32(As[(rb + 8 + g) * AS_LD + kk * 8 + tig]);
                afr[mt][2] = cvt_tf32(As[(rb + g) * AS_LD + kk * 8 + 4 + tig]);
                afr[mt][3] = cvt_tf32(As[(rb + 8 + g) * AS_LD + kk * 8 + 4 + tig]);
            }
            unsigned bfr[8][2];
            #pragma unroll
            for (int nt2 = 0; nt2 < 8; nt2++) {
                const int cb = warp_n * 64 + nt2 * 8 + g;
                bfr[nt2][0] = cvt_tf32(Bs[(kk * 8 + tig) * BS_LD + cb]);
                bfr[nt2][1] = cvt_tf32(Bs[(kk * 8 + 4 + tig) * BS_LD + cb]);
            }
            #pragma unroll
            for (int mt = 0; mt < 2; mt++)
                #pragma unroll
                for (int nt2 = 0; nt2 < 8; nt2++)
                    mma_tf32(acc[mt][nt2], afr[mt], bfr[nt2]);
        }
        __syncthreads();
    }

    // ---- epilogue: bias + store ----
    #pragma unroll
    for (int mt = 0; mt < 2; mt++) {
        const int r0 = m0 + warp_m * 32 + mt * 16 + g;
        #pragma unroll
        for (int nt2 = 0; nt2 < 8; nt2++) {
            const int col = n0 + warp_n * 64 + nt2 * 8 + 2 * tig;
            const float b0 = bias[col], b1 = bias[col + 1];
            float2 v0 = make_float2(acc[mt][nt2][0] + b0, acc[mt][nt2][1] + b1);
            float2 v1 = make_float2(acc[mt][nt2][2] + b0, acc[mt][nt2][3] + b1);
            *(float2*)(out + (long)r0 * N_DIM + col)       = v0;
            *(float2*)(out + (long)(r0 + 8) * N_DIM + col) = v1;
        }
    }
}

// ---------------------------------------------------------------------------
extern "C" void kernel_launch(void* const* d_in, const int* in_sizes, int n_in,
                              void* d_out, int out_size) {
    const float* x = (const float*)d_in[0];   // [128,3,224,224]
    const float* w = (const float*)d_in[1];   // [768,3,16,16]
    const float* b = (const float*)d_in[2];   // [768]
    float* out = (float*)d_out;               // [128,196,768]

    cudaFuncSetAttribute(gemm_tf32_kernel,
                         cudaFuncAttributeMaxDynamicSharedMemorySize, SMEM_BYTES);

    dct_weight_kernel<<<N_DIM * CHAN, 256>>>(w);
    gemm_tf32_kernel<<<dim3(N_DIM / BN, M_DIM / BM), 256, SMEM_BYTES>>>(x, b, out);
}

// round 5
// speedup vs baseline: 2.4605x; 1.0305x over previous
#include <cuda_runtime.h>
#include <math.h>
#include <stdint.h>

// ---------------- problem constants ----------------
#define BATCH   128
#define CHAN    3
#define HW      224
#define PATCH   16
#define NPD     14
#define NPATCH  (NPD*NPD)           // 196
#define M_DIM   (BATCH*NPATCH)      // 25088
#define K_DIM   (CHAN*PATCH*PATCH)  // 768
#define N_DIM   768
#define IMG_STRIDE (CHAN*HW*HW)     // 150528
#define CH_STRIDE  (HW*HW)          // 50176

#define PI_D 3.141592653589793238462643383279502884

// DCT-folded, tf32-pre-rounded weights, layout [n][k]
__device__ float g_wt[N_DIM * K_DIM];

__device__ __forceinline__ float tf32r(float f) {
    uint32_t u; asm("cvt.rna.tf32.f32 %0, %1;" : "=r"(u) : "f"(f));
    return __uint_as_float(u);
}
__device__ __forceinline__ unsigned cvt_tf32(float f) {
    unsigned r; asm("cvt.rna.tf32.f32 %0, %1;" : "=r"(r) : "f"(f));
    return r;
}
__device__ __forceinline__ void mma_tf32(float* c, const unsigned* a, const unsigned* b) {
    asm volatile(
        "mma.sync.aligned.m16n8k8.row.col.f32.tf32.tf32.f32 "
        "{%0,%1,%2,%3}, {%4,%5,%6,%7}, {%8,%9}, {%0,%1,%2,%3};"
        : "+f"(c[0]), "+f"(c[1]), "+f"(c[2]), "+f"(c[3])
        : "r"(a[0]), "r"(a[1]), "r"(a[2]), "r"(a[3]), "r"(b[0]), "r"(b[1]));
}
#define CP_ASYNC16(saddr, gptr) \
    asm volatile("cp.async.cg.shared.global [%0], [%1], 16;" :: "r"(saddr), "l"(gptr))
#define CP_COMMIT()  asm volatile("cp.async.commit_group;" ::: "memory")
#define CP_WAIT(n)   asm volatile("cp.async.wait_group %0;" :: "n"(n) : "memory")

// ---------------------------------------------------------------------------
// Kernel 1: fold per-8x8 DCT into conv weights (w' = D^T W D), tf32-round,
// store transposed as [n][k] so GEMM B loads are K-major contiguous.
// ---------------------------------------------------------------------------
__global__ void dct_weight_kernel(const float* __restrict__ w) {
    __shared__ float Ws[16][16];
    __shared__ float Ds[8][8];
    int o = blockIdx.x / CHAN, c = blockIdx.x % CHAN, tid = threadIdx.x;
    if (tid < 64) {
        int k = tid >> 3, n = tid & 7;
        double v = sqrt(2.0 / 8.0) * cos(PI_D * (2.0 * n + 1.0) * k / 16.0);
        if (k == 0) v *= (1.0 / sqrt(2.0));
        Ds[k][n] = (float)v;
    }
    Ws[tid >> 4][tid & 15] = w[(o * CHAN + c) * 256 + tid];
    __syncthreads();
    int i = tid >> 4, j = tid & 15;
    int bi = i & 8, bj = j & 8, ii = i & 7, jj = j & 7;
    float s = 0.0f;
    #pragma unroll
    for (int u = 0; u < 8; u++) {
        float du = Ds[u][ii];
        #pragma unroll
        for (int v = 0; v < 8; v++) s += du * Ws[bi + u][bj + v] * Ds[v][jj];
    }
    g_wt[(long)o * K_DIM + c * 256 + i * 16 + j] = tf32r(s);
}

// ---------------------------------------------------------------------------
// Kernel 2: tf32 mma.sync GEMM, issue-optimized.
//   BM=128 BN=128 BK=32, 4-stage cp.async, 8 warps (4m x 2n), warp tile 32x64.
//   K-major smem, 40-float row stride (conflict-free LDS.64),
//   fragment-k relabeling: logical (2t,2t+1) -> fragment (t,t+4) so every
//   fragment pair is one LDS.64. B pre-rounded (no CVT); A CVT only.
// ---------------------------------------------------------------------------
#define BM 128
#define BN 128
#define BK 32
#define STAGES 4
#define NT (K_DIM / BK)         // 24
#define ROWF 40                 // floats per smem row (32 data + 8 pad)
#define TILE_F (BM * ROWF)      // 5120 floats per operand tile
#define STG_F (2 * TILE_F)      // A then B
#define SMEM_BYTES (STAGES * STG_F * 4)   // 163840

__global__ __launch_bounds__(256)
void gemm_tf32_kernel(const float* __restrict__ x,
                      const float* __restrict__ bias,
                      float* __restrict__ out) {
    extern __shared__ float smem[];
    const int tid  = threadIdx.x;
    const int lane = tid & 31, wid = tid >> 5;
    const int warp_m = wid >> 1, warp_n = wid & 1;
    const int g = lane >> 2, tig = lane & 3;

    const int m0 = blockIdx.y * BM;
    const int n0 = blockIdx.x * BN;

    // ---- global-load mapping: per operand 1024 16B chunks, 4 per thread ----
    const int arow = tid >> 3;     // 0..31 ; rows arow + 32*s
    const int q    = tid & 7;      // 16B chunk within the 32-float k row
    const int kq4  = q >> 2;       // extra patch-row (k 16..31)
    const int jof  = (q & 3) * 4;  // column offset inside patch row

    long abase[4];
    #pragma unroll
    for (int s = 0; s < 4; s++) {
        int m = m0 + arow + 32 * s;
        int b = m / NPATCH, pr = m % NPATCH;
        abase[s] = (long)b * IMG_STRIDE + (long)(pr / NPD) * (PATCH * HW)
                 + (long)(pr % NPD) * PATCH;
    }
    const float* gB = g_wt + (long)(n0 + arow) * K_DIM + q * 4;

    auto load_tile = [&](int t, int slot) {
        float* As = smem + slot * STG_F;
        float* Bs = As + TILE_F;
        const int k0 = t * BK;
        const int c  = k0 >> 8;
        const int i0 = (k0 & 255) >> 4;
        const long aoff = (long)c * CH_STRIDE + (long)(i0 + kq4) * HW + jof;
        #pragma unroll
        for (int s = 0; s < 4; s++) {
            unsigned sa = (unsigned)__cvta_generic_to_shared(
                &As[(arow + 32 * s) * ROWF + q * 4]);
            CP_ASYNC16(sa, x + abase[s] + aoff);
        }
        #pragma unroll
        for (int s = 0; s < 4; s++) {
            unsigned sb = (unsigned)__cvta_generic_to_shared(
                &Bs[(arow + 32 * s) * ROWF + q * 4]);
            CP_ASYNC16(sb, gB + k0 + (long)(32 * s) * K_DIM);
        }
    };

    float acc[2][8][4];
    #pragma unroll
    for (int i = 0; i < 2; i++)
        #pragma unroll
        for (int j = 0; j < 8; j++)
            #pragma unroll
            for (int p = 0; p < 4; p++) acc[i][j][p] = 0.0f;

    #pragma unroll
    for (int s = 0; s < STAGES - 1; s++) { load_tile(s, s); CP_COMMIT(); }

    // per-warp fragment base offsets (floats)
    const int aoffm = (warp_m * 32 + g) * ROWF + 2 * tig;
    const int boffn = (warp_n * 64 + g) * ROWF + 2 * tig;

    for (int t = 0; t < NT; t++) {
        CP_WAIT(STAGES - 2);
        __syncthreads();

        const int tn = t + STAGES - 1;
        if (tn < NT) load_tile(tn, tn % STAGES);
        CP_COMMIT();

        const float* As = smem + (t % STAGES) * STG_F;
        const float* Bs = As + TILE_F;

        #pragma unroll
        for (int kk = 0; kk < 4; kk++) {
            // A fragments: 2 LDS.64 per m-tile, CVT to tf32
            unsigned afr[2][4];
            #pragma unroll
            for (int mt = 0; mt < 2; mt++) {
                float2 p0 = *(const float2*)(As + aoffm + mt * 16 * ROWF + kk * 8);
                float2 p1 = *(const float2*)(As + aoffm + (mt * 16 + 8) * ROWF + kk * 8);
                afr[mt][0] = cvt_tf32(p0.x);   // fragment k = tig      (logical 2tig)
                afr[mt][2] = cvt_tf32(p0.y);   // fragment k = tig+4    (logical 2tig+1)
                afr[mt][1] = cvt_tf32(p1.x);
                afr[mt][3] = cvt_tf32(p1.y);
            }
            // B fragments: 1 LDS.64 each, pre-rounded -> raw bits
            unsigned bfr[8][2];
            #pragma unroll
            for (int nt = 0; nt < 8; nt++) {
                uint2 qv = *(const uint2*)(Bs + boffn + nt * 8 * ROWF + kk * 8);
                bfr[nt][0] = qv.x;
                bfr[nt][1] = qv.y;
            }
            #pragma unroll
            for (int mt = 0; mt < 2; mt++)
                #pragma unroll
                for (int nt = 0; nt < 8; nt++)
                    mma_tf32(acc[mt][nt], afr[mt], bfr[nt]);
        }
        __syncthreads();
    }

    // ---- epilogue: bias + store ----
    #pragma unroll
    for (int mt = 0; mt < 2; mt++) {
        const int r0 = m0 + warp_m * 32 + mt * 16 + g;
        #pragma unroll
        for (int nt = 0; nt < 8; nt++) {
            const int col = n0 + warp_n * 64 + nt * 8 + 2 * tig;
            const float b0 = bias[col], b1 = bias[col + 1];
            float2 v0 = make_float2(acc[mt][nt][0] + b0, acc[mt][nt][1] + b1);
            float2 v1 = make_float2(acc[mt][nt][2] + b0, acc[mt][nt][3] + b1);
            *(float2*)(out + (long)r0 * N_DIM + col)       = v0;
            *(float2*)(out + (long)(r0 + 8) * N_DIM + col) = v1;
        }
    }
}

// ---------------------------------------------------------------------------
extern "C" void kernel_launch(void* const* d_in, const int* in_sizes, int n_in,
                              void* d_out, int out_size) {
    const float* x = (const float*)d_in[0];   // [128,3,224,224]
    const float* w = (const float*)d_in[1];   // [768,3,16,16]
    const float* b = (const float*)d_in[2];   // [768]
    float* out = (float*)d_out;               // [128,196,768]

    cudaFuncSetAttribute(gemm_tf32_kernel,
                         cudaFuncAttributeMaxDynamicSharedMemorySize, SMEM_BYTES);

    dct_weight_kernel<<<N_DIM * CHAN, 256>>>(w);
    gemm_tf32_kernel<<<dim3(N_DIM / BN, M_DIM / BM), 256, SMEM_BYTES>>>(x, b, out);
}

// round 6
// speedup vs baseline: 2.9793x; 1.2109x over previous
#include <cuda_runtime.h>
#include <math.h>
#include <stdint.h>

// ---------------- problem constants ----------------
#define BATCH   128
#define CHAN    3
#define HW      224
#define PATCH   16
#define NPD     14
#define NPATCH  (NPD*NPD)           // 196
#define M_DIM   (BATCH*NPATCH)      // 25088
#define K_DIM   (CHAN*PATCH*PATCH)  // 768
#define N_DIM   768
#define IMG_STRIDE (CHAN*HW*HW)     // 150528
#define CH_STRIDE  (HW*HW)          // 50176

#define PI_D 3.141592653589793238462643383279502884

// DCT-folded, tf32-pre-rounded weights, layout [n][k]
__device__ float g_wt[N_DIM * K_DIM];

__device__ __forceinline__ float tf32r(float f) {
    uint32_t u; asm("cvt.rna.tf32.f32 %0, %1;" : "=r"(u) : "f"(f));
    return __uint_as_float(u);
}
__device__ __forceinline__ unsigned cvt_tf32(float f) {
    unsigned r; asm("cvt.rna.tf32.f32 %0, %1;" : "=r"(r) : "f"(f));
    return r;
}
__device__ __forceinline__ void mma_tf32(float* c, const unsigned* a, const unsigned* b) {
    asm volatile(
        "mma.sync.aligned.m16n8k8.row.col.f32.tf32.tf32.f32 "
        "{%0,%1,%2,%3}, {%4,%5,%6,%7}, {%8,%9}, {%0,%1,%2,%3};"
        : "+f"(c[0]), "+f"(c[1]), "+f"(c[2]), "+f"(c[3])
        : "r"(a[0]), "r"(a[1]), "r"(a[2]), "r"(a[3]), "r"(b[0]), "r"(b[1]));
}
#define CP_ASYNC16(saddr, gptr) \
    asm volatile("cp.async.cg.shared.global [%0], [%1], 16;" :: "r"(saddr), "l"(gptr))
#define CP_COMMIT()  asm volatile("cp.async.commit_group;" ::: "memory")
#define CP_WAIT(n)   asm volatile("cp.async.wait_group %0;" :: "n"(n) : "memory")

// ---------------------------------------------------------------------------
// Kernel 1: fold per-8x8 DCT into conv weights (w' = D^T W D), tf32-round,
// store transposed as [n][k] so GEMM B loads are K-major contiguous.
// ---------------------------------------------------------------------------
__global__ void dct_weight_kernel(const float* __restrict__ w) {
    __shared__ float Ws[16][16];
    __shared__ float Ds[8][8];
    int o = blockIdx.x / CHAN, c = blockIdx.x % CHAN, tid = threadIdx.x;
    if (tid < 64) {
        int k = tid >> 3, n = tid & 7;
        double v = sqrt(2.0 / 8.0) * cos(PI_D * (2.0 * n + 1.0) * k / 16.0);
        if (k == 0) v *= (1.0 / sqrt(2.0));
        Ds[k][n] = (float)v;
    }
    Ws[tid >> 4][tid & 15] = w[(o * CHAN + c) * 256 + tid];
    __syncthreads();
    int i = tid >> 4, j = tid & 15;
    int bi = i & 8, bj = j & 8, ii = i & 7, jj = j & 7;
    float s = 0.0f;
    #pragma unroll
    for (int u = 0; u < 8; u++) {
        float du = Ds[u][ii];
        #pragma unroll
        for (int v = 0; v < 8; v++) s += du * Ws[bi + u][bj + v] * Ds[v][jj];
    }
    g_wt[(long)o * K_DIM + c * 256 + i * 16 + j] = tf32r(s);
}

// ---------------------------------------------------------------------------
// Kernel 2: tf32 mma.sync GEMM.
//   BM=128 BN=128 BK=32, 2-stage cp.async, 2 CTAs/SM (occupancy for latency
//   hiding), 8 warps (4m x 2n), warp tile 32x64.
//   K-major smem, 40-float row stride (conflict-free LDS.64),
//   fragment-k relabeling: logical (2t,2t+1) -> fragment (t,t+4) so every
//   fragment pair is one LDS.64. B pre-rounded (no CVT); A CVT only.
//   Main loop unrolled x2 -> stage offsets are compile-time.
// ---------------------------------------------------------------------------
#define BM 128
#define BN 128
#define BK 32
#define STAGES 2
#define NT (K_DIM / BK)         // 24
#define ROWF 40                 // floats per smem row (32 data + 8 pad)
#define TILE_F (BM * ROWF)      // 5120 floats per operand tile
#define STG_F (2 * TILE_F)      // A then B
#define SMEM_BYTES (STAGES * STG_F * 4)   // 81920

__global__ __launch_bounds__(256, 2)
void gemm_tf32_kernel(const float* __restrict__ x,
                      const float* __restrict__ bias,
                      float* __restrict__ out) {
    extern __shared__ float smem[];
    const int tid  = threadIdx.x;
    const int lane = tid & 31, wid = tid >> 5;
    const int warp_m = wid >> 1, warp_n = wid & 1;
    const int g = lane >> 2, tig = lane & 3;

    const int m0 = blockIdx.y * BM;
    const int n0 = blockIdx.x * BN;

    // ---- global-load mapping: per operand 1024 16B chunks, 4 per thread ----
    const int arow = tid >> 3;     // 0..31 ; rows arow + 32*s
    const int q    = tid & 7;      // 16B chunk within the 32-float k row
    const int kq4  = q >> 2;       // extra patch-row (k 16..31)
    const int jof  = (q & 3) * 4;  // column offset inside patch row

    long abase[4];
    #pragma unroll
    for (int s = 0; s < 4; s++) {
        int m = m0 + arow + 32 * s;
        int b = m / NPATCH, pr = m % NPATCH;
        abase[s] = (long)b * IMG_STRIDE + (long)(pr / NPD) * (PATCH * HW)
                 + (long)(pr % NPD) * PATCH;
    }
    const float* gB = g_wt + (long)(n0 + arow) * K_DIM + q * 4;

    // precomputed smem store addresses for both slots
    unsigned sa_addr[2][4], sb_addr[2][4];
    #pragma unroll
    for (int sl = 0; sl < 2; sl++) {
        float* As = smem + sl * STG_F;
        float* Bs = As + TILE_F;
        #pragma unroll
        for (int s = 0; s < 4; s++) {
            sa_addr[sl][s] = (unsigned)__cvta_generic_to_shared(
                &As[(arow + 32 * s) * ROWF + q * 4]);
            sb_addr[sl][s] = (unsigned)__cvta_generic_to_shared(
                &Bs[(arow + 32 * s) * ROWF + q * 4]);
        }
    }

    auto load_tile = [&](int t, int slot) {
        const int k0 = t * BK;
        const int c  = k0 >> 8;
        const int i0 = (k0 & 255) >> 4;
        const long aoff = (long)c * CH_STRIDE + (long)(i0 + kq4) * HW + jof;
        #pragma unroll
        for (int s = 0; s < 4; s++)
            CP_ASYNC16(sa_addr[slot][s], x + abase[s] + aoff);
        #pragma unroll
        for (int s = 0; s < 4; s++)
            CP_ASYNC16(sb_addr[slot][s], gB + k0 + (long)(32 * s) * K_DIM);
    };

    float acc[2][8][4];
    #pragma unroll
    for (int i = 0; i < 2; i++)
        #pragma unroll
        for (int j = 0; j < 8; j++)
            #pragma unroll
            for (int p = 0; p < 4; p++) acc[i][j][p] = 0.0f;

    load_tile(0, 0);
    CP_COMMIT();

    // per-warp fragment base offsets (floats)
    const int aoffm = (warp_m * 32 + g) * ROWF + 2 * tig;
    const int boffn = (warp_n * 64 + g) * ROWF + 2 * tig;

    auto compute_tile = [&](const float* __restrict__ As) {
        const float* Bs = As + TILE_F;
        #pragma unroll
        for (int kk = 0; kk < 4; kk++) {
            unsigned afr[2][4];
            #pragma unroll
            for (int mt = 0; mt < 2; mt++) {
                float2 p0 = *(const float2*)(As + aoffm + mt * 16 * ROWF + kk * 8);
                float2 p1 = *(const float2*)(As + aoffm + (mt * 16 + 8) * ROWF + kk * 8);
                afr[mt][0] = cvt_tf32(p0.x);   // fragment k = tig      (logical 2tig)
                afr[mt][2] = cvt_tf32(p0.y);   // fragment k = tig+4    (logical 2tig+1)
                afr[mt][1] = cvt_tf32(p1.x);
                afr[mt][3] = cvt_tf32(p1.y);
            }
            unsigned bfr[8][2];
            #pragma unroll
            for (int nt = 0; nt < 8; nt++) {
                uint2 qv = *(const uint2*)(Bs + boffn + nt * 8 * ROWF + kk * 8);
                bfr[nt][0] = qv.x;
                bfr[nt][1] = qv.y;
            }
            #pragma unroll
            for (int mt = 0; mt < 2; mt++)
                #pragma unroll
                for (int nt = 0; nt < 8; nt++)
                    mma_tf32(acc[mt][nt], afr[mt], bfr[nt]);
        }
    };

    // main loop, unrolled x2 (NT = 24, even): slots alternate 0,1 at
    // compile-time so all smem offsets are immediates.
    for (int t = 0; t < NT; t += 2) {
        // --- even tile: compute slot 0, prefetch t+1 into slot 1 ---
        CP_WAIT(0);
        __syncthreads();
        if (t + 1 < NT) load_tile(t + 1, 1);
        CP_COMMIT();
        compute_tile(smem);
        __syncthreads();

        // --- odd tile: compute slot 1, prefetch t+2 into slot 0 ---
        CP_WAIT(0);
        __syncthreads();
        if (t + 2 < NT) load_tile(t + 2, 0);
        CP_COMMIT();
        compute_tile(smem + STG_F);
        __syncthreads();
    }

    // ---- epilogue: bias + store ----
    #pragma unroll
    for (int mt = 0; mt < 2; mt++) {
        const int r0 = m0 + warp_m * 32 + mt * 16 + g;
        #pragma unroll
        for (int nt = 0; nt < 8; nt++) {
            const int col = n0 + warp_n * 64 + nt * 8 + 2 * tig;
            const float b0 = bias[col], b1 = bias[col + 1];
            float2 v0 = make_float2(acc[mt][nt][0] + b0, acc[mt][nt][1] + b1);
            float2 v1 = make_float2(acc[mt][nt][2] + b0, acc[mt][nt][3] + b1);
            *(float2*)(out + (long)r0 * N_DIM + col)       = v0;
            *(float2*)(out + (long)(r0 + 8) * N_DIM + col) = v1;
        }
    }
}

// ---------------------------------------------------------------------------
extern "C" void kernel_launch(void* const* d_in, const int* in_sizes, int n_in,
                              void* d_out, int out_size) {
    const float* x = (const float*)d_in[0];   // [128,3,224,224]
    const float* w = (const float*)d_in[1];   // [768,3,16,16]
    const float* b = (const float*)d_in[2];   // [768]
    float* out = (float*)d_out;               // [128,196,768]

    cudaFuncSetAttribute(gemm_tf32_kernel,
                         cudaFuncAttributeMaxDynamicSharedMemorySize, SMEM_BYTES);

    dct_weight_kernel<<<N_DIM * CHAN, 256>>>(w);
    gemm_tf32_kernel<<<dim3(N_DIM / BN, M_DIM / BM), 256, SMEM_BYTES>>>(x, b, out);
}

// round 7
// speedup vs baseline: 4.4004x; 1.4770x over previous
#include <cuda_runtime.h>
#include <cuda_fp16.h>
#include <math.h>
#include <stdint.h>

// ---------------- problem constants ----------------
#define BATCH   128
#define CHAN    3
#define HW      224
#define PATCH   16
#define NPD     14
#define NPATCH  (NPD*NPD)           // 196
#define M_DIM   (BATCH*NPATCH)      // 25088
#define K_DIM   (CHAN*PATCH*PATCH)  // 768
#define N_DIM   768

#define PI_D 3.141592653589793238462643383279502884

// fp16 scratch: DCT-folded weights [n][k]; im2col'd input [m][k]
__device__ __half g_wt[N_DIM * K_DIM];
__device__ __half g_xh[(long)M_DIM * K_DIM];

__device__ __forceinline__ void mma_f16(float* c, const unsigned* a, const unsigned* b) {
    asm volatile(
        "mma.sync.aligned.m16n8k16.row.col.f32.f16.f16.f32 "
        "{%0,%1,%2,%3}, {%4,%5,%6,%7}, {%8,%9}, {%0,%1,%2,%3};"
        : "+f"(c[0]), "+f"(c[1]), "+f"(c[2]), "+f"(c[3])
        : "r"(a[0]), "r"(a[1]), "r"(a[2]), "r"(a[3]), "r"(b[0]), "r"(b[1]));
}
#define CP_ASYNC16(saddr, gptr) \
    asm volatile("cp.async.cg.shared.global [%0], [%1], 16;" :: "r"(saddr), "l"(gptr))
#define CP_COMMIT()  asm volatile("cp.async.commit_group;" ::: "memory")
#define CP_WAIT(n)   asm volatile("cp.async.wait_group %0;" :: "n"(n) : "memory")

// ---------------------------------------------------------------------------
// Kernel 0: im2col x (fp32 NCHW) -> g_xh (fp16, [m][k]).  One float4 per thread.
// ---------------------------------------------------------------------------
__global__ void im2col_h_kernel(const float* __restrict__ x) {
    int f = blockIdx.x * blockDim.x + threadIdx.x;      // float4 index
    float4 v = ((const float4*)x)[f];
    int w4 = f % 56; int rest = f / 56;
    int h = rest % HW; rest /= HW;
    int c = rest % CHAN; int b = rest / CHAN;
    int j = (w4 * 4) & 15, pw = (w4 * 4) >> 4;
    int i = h & 15,        ph = h >> 4;
    long m = (long)b * NPATCH + ph * NPD + pw;
    int  k = c * 256 + i * 16 + j;
    __half2 h0 = __floats2half2_rn(v.x, v.y);
    __half2 h1 = __floats2half2_rn(v.z, v.w);
    uint2 out;
    out.x = *(unsigned*)&h0;
    out.y = *(unsigned*)&h1;
    *(uint2*)(g_xh + m * K_DIM + k) = out;     // 8B aligned: j in {0,4,8,12}
}

// ---------------------------------------------------------------------------
// Kernel 1: fold per-8x8 DCT into conv weights (w' = D^T W D), fp16, [n][k].
// ---------------------------------------------------------------------------
__global__ void dct_weight_kernel(const float* __restrict__ w) {
    __shared__ float Ws[16][16];
    __shared__ float Ds[8][8];
    int o = blockIdx.x / CHAN, c = blockIdx.x % CHAN, tid = threadIdx.x;
    if (tid < 64) {
        int k = tid >> 3, n = tid & 7;
        double v = sqrt(2.0 / 8.0) * cos(PI_D * (2.0 * n + 1.0) * k / 16.0);
        if (k == 0) v *= (1.0 / sqrt(2.0));
        Ds[k][n] = (float)v;
    }
    Ws[tid >> 4][tid & 15] = w[(o * CHAN + c) * 256 + tid];
    __syncthreads();
    int i = tid >> 4, j = tid & 15;
    int bi = i & 8, bj = j & 8, ii = i & 7, jj = j & 7;
    float s = 0.0f;
    #pragma unroll
    for (int u = 0; u < 8; u++) {
        float du = Ds[u][ii];
        #pragma unroll
        for (int v = 0; v < 8; v++) s += du * Ws[bi + u][bj + v] * Ds[v][jj];
    }
    g_wt[(long)o * K_DIM + c * 256 + i * 16 + j] = __float2half_rn(s);
}

// ---------------------------------------------------------------------------
// Kernel 2: fp16 mma.sync m16n8k16 GEMM.
//   BM=128 BN=128 BK=32, 4-stage cp.async, 2 CTAs/SM, 8 warps (4m x 2n),
//   warp tile 32x64.  K-major fp16 smem, 48-half row stride (conflict-free
//   LDS.64 fragment loads).  Natural contiguous storage; fragment pairing
//   (storage pair 2t -> frag t, 2t+1 -> frag t+4) applied to both A and B.
// ---------------------------------------------------------------------------
#define BM 128
#define BN 128
#define BK 32
#define STAGES 4
#define NT (K_DIM / BK)          // 24
#define ROWH 48                  // halves per smem row (32 data + 16 pad) = 96B
#define TILE_H (BM * ROWH)       // 6144 halves per operand tile
#define STG_H (2 * TILE_H)       // A then B
#define SMEM_BYTES (STAGES * STG_H * 2)   // 98304

__global__ __launch_bounds__(256, 2)
void gemm_f16_kernel(const float* __restrict__ bias, float* __restrict__ out) {
    extern __shared__ __half smem[];
    const int tid  = threadIdx.x;
    const int lane = tid & 31, wid = tid >> 5;
    const int warp_m = wid >> 1, warp_n = wid & 1;
    const int g = lane >> 2, tig = lane & 3;

    const int m0 = blockIdx.y * BM;
    const int n0 = blockIdx.x * BN;

    // ---- global-load mapping: per operand 512 16B chunks, 2 per thread ----
    // chunk idx = tid + 256*s : row = idx>>2 (0..127), q = idx&3
    const int row0 = tid >> 2;      // rows row0, row0+64
    const int q    = tid & 3;       // 16B chunk within 64B k-row

    const __half* gA0 = g_xh + (long)(m0 + row0) * K_DIM + q * 8;
    const __half* gA1 = g_xh + (long)(m0 + row0 + 64) * K_DIM + q * 8;
    const __half* gB0 = g_wt + (long)(n0 + row0) * K_DIM + q * 8;
    const __half* gB1 = g_wt + (long)(n0 + row0 + 64) * K_DIM + q * 8;

    // smem byte offsets (per slot): row*96 + q*16
    unsigned sa0[STAGES], sa1[STAGES], sb0[STAGES], sb1[STAGES];
    #pragma unroll
    for (int sl = 0; sl < STAGES; sl++) {
        unsigned base = (unsigned)__cvta_generic_to_shared(smem) + sl * STG_H * 2;
        sa0[sl] = base + row0 * 96 + q * 16;
        sa1[sl] = base + (row0 + 64) * 96 + q * 16;
        sb0[sl] = base + TILE_H * 2 + row0 * 96 + q * 16;
        sb1[sl] = base + TILE_H * 2 + (row0 + 64) * 96 + q * 16;
    }

    auto load_tile = [&](int t, int slot) {
        const int k0 = t * BK;
        CP_ASYNC16(sa0[slot], gA0 + k0);
        CP_ASYNC16(sa1[slot], gA1 + k0);
        CP_ASYNC16(sb0[slot], gB0 + k0);
        CP_ASYNC16(sb1[slot], gB1 + k0);
    };

    float acc[2][8][4];
    #pragma unroll
    for (int i = 0; i < 2; i++)
        #pragma unroll
        for (int j = 0; j < 8; j++)
            #pragma unroll
            for (int p = 0; p < 4; p++) acc[i][j][p] = 0.0f;

    #pragma unroll
    for (int s = 0; s < STAGES - 1; s++) { load_tile(s, s); CP_COMMIT(); }

    // fragment base offsets (halves)
    const int aoffm = (warp_m * 32 + g) * ROWH + 4 * tig;
    const int boffn = (warp_n * 64 + g) * ROWH + 4 * tig;

    auto compute_tile = [&](const __half* __restrict__ As) {
        const __half* Bs = As + TILE_H;
        #pragma unroll
        for (int kk = 0; kk < 2; kk++) {      // two k16 steps per BK=32
            unsigned afr[2][4];
            #pragma unroll
            for (int mt = 0; mt < 2; mt++) {
                uint2 p0 = *(const uint2*)(As + aoffm + mt * 16 * ROWH + kk * 16);
                uint2 p1 = *(const uint2*)(As + aoffm + (mt * 16 + 8) * ROWH + kk * 16);
                afr[mt][0] = p0.x;   // row g,   frag k-pair tig
                afr[mt][2] = p0.y;   // row g,   frag k-pair tig+4
                afr[mt][1] = p1.x;   // row g+8, frag k-pair tig
                afr[mt][3] = p1.y;   // row g+8, frag k-pair tig+4
            }
            unsigned bfr[8][2];
            #pragma unroll
            for (int nt = 0; nt < 8; nt++) {
                uint2 qv = *(const uint2*)(Bs + boffn + nt * 8 * ROWH + kk * 16);
                bfr[nt][0] = qv.x;
                bfr[nt][1] = qv.y;
            }
            #pragma unroll
            for (int mt = 0; mt < 2; mt++)
                #pragma unroll
                for (int nt = 0; nt < 8; nt++)
                    mma_f16(acc[mt][nt], afr[mt], bfr[nt]);
        }
    };

    // main loop: NT=24, unrolled by STAGES so slots are compile-time
    for (int t0 = 0; t0 < NT; t0 += STAGES) {
        #pragma unroll
        for (int u = 0; u < STAGES; u++) {
            const int t = t0 + u;
            CP_WAIT(STAGES - 2);
            __syncthreads();
            const int tn = t + STAGES - 1;
            if (tn < NT) load_tile(tn, tn & (STAGES - 1));
            CP_COMMIT();
            compute_tile(smem + u * STG_H);
            __syncthreads();
        }
    }

    // ---- epilogue: bias + store ----
    #pragma unroll
    for (int mt = 0; mt < 2; mt++) {
        const int r0 = m0 + warp_m * 32 + mt * 16 + g;
        #pragma unroll
        for (int nt = 0; nt < 8; nt++) {
            const int col = n0 + warp_n * 64 + nt * 8 + 2 * tig;
            const float b0 = bias[col], b1 = bias[col + 1];
            float2 v0 = make_float2(acc[mt][nt][0] + b0, acc[mt][nt][1] + b1);
            float2 v1 = make_float2(acc[mt][nt][2] + b0, acc[mt][nt][3] + b1);
            *(float2*)(out + (long)r0 * N_DIM + col)       = v0;
            *(float2*)(out + (long)(r0 + 8) * N_DIM + col) = v1;
        }
    }
}

// ---------------------------------------------------------------------------
extern "C" void kernel_launch(void* const* d_in, const int* in_sizes, int n_in,
                              void* d_out, int out_size) {
    const float* x = (const float*)d_in[0];   // [128,3,224,224]
    const float* w = (const float*)d_in[1];   // [768,3,16,16]
    const float* b = (const float*)d_in[2];   // [768]
    float* out = (float*)d_out;               // [128,196,768]

    cudaFuncSetAttribute(gemm_f16_kernel,
                         cudaFuncAttributeMaxDynamicSharedMemorySize, SMEM_BYTES);

    const int NF4 = BATCH * CHAN * HW * HW / 4;   // 4,816,896
    im2col_h_kernel<<<NF4 / 256, 256>>>(x);
    dct_weight_kernel<<<N_DIM * CHAN, 256>>>(w);
    gemm_f16_kernel<<<dim3(N_DIM / BN, M_DIM / BM), 256, SMEM_BYTES>>>(b, out);
}

// round 10
// speedup vs baseline: 5.0351x; 1.1443x over previous
#include <cuda_runtime.h>
#include <cuda_fp16.h>
#include <math.h>
#include <stdint.h>

// ---------------- problem constants ----------------
#define BATCH   128
#define CHAN    3
#define HW      224
#define PATCH   16
#define NPD     14
#define NPATCH  (NPD*NPD)           // 196
#define M_DIM   (BATCH*NPATCH)      // 25088
#define K_DIM   (CHAN*PATCH*PATCH)  // 768
#define N_DIM   768

#define PI_D 3.141592653589793238462643383279502884

// fp16 scratch: DCT-folded weights [n][k]; im2col'd input [m][k]
__device__ __half g_wt[N_DIM * K_DIM];
__device__ __half g_xh[(long)M_DIM * K_DIM];

__device__ __forceinline__ void mma_f16(float* c, const unsigned* a, const unsigned* b) {
    asm volatile(
        "mma.sync.aligned.m16n8k16.row.col.f32.f16.f16.f32 "
        "{%0,%1,%2,%3}, {%4,%5,%6,%7}, {%8,%9}, {%0,%1,%2,%3};"
        : "+f"(c[0]), "+f"(c[1]), "+f"(c[2]), "+f"(c[3])
        : "r"(a[0]), "r"(a[1]), "r"(a[2]), "r"(a[3]), "r"(b[0]), "r"(b[1]));
}
#define LDSM_X4(r0, r1, r2, r3, addr) \
    asm volatile("ldmatrix.sync.aligned.m8n8.x4.shared.b16 {%0,%1,%2,%3}, [%4];" \
                 : "=r"(r0), "=r"(r1), "=r"(r2), "=r"(r3) : "r"(addr))
#define CP_ASYNC16(saddr, gptr) \
    asm volatile("cp.async.cg.shared.global [%0], [%1], 16;" :: "r"(saddr), "l"(gptr))
#define CP_COMMIT()  asm volatile("cp.async.commit_group;" ::: "memory")
#define CP_WAIT(n)   asm volatile("cp.async.wait_group %0;" :: "n"(n) : "memory")

// ---------------------------------------------------------------------------
// Kernel 0: im2col x (fp32 NCHW) -> g_xh (fp16, [m][k]).  8 floats per thread.
// ---------------------------------------------------------------------------
__global__ void im2col_h_kernel(const float* __restrict__ x) {
    int f = blockIdx.x * blockDim.x + threadIdx.x;      // 8-float chunk index
    const float4* xp = (const float4*)x + (long)f * 2;
    float4 v0 = xp[0], v1 = xp[1];
    int w8 = f % 28; int rest = f / 28;
    int h = rest % HW; rest /= HW;
    int c = rest % CHAN; int b = rest / CHAN;
    int j = (w8 * 8) & 15, pw = (w8 * 8) >> 4;
    int i = h & 15,        ph = h >> 4;
    long m = (long)b * NPATCH + ph * NPD + pw;
    int  k = c * 256 + i * 16 + j;
    __half2 h0 = __floats2half2_rn(v0.x, v0.y);
    __half2 h1 = __floats2half2_rn(v0.z, v0.w);
    __half2 h2 = __floats2half2_rn(v1.x, v1.y);
    __half2 h3 = __floats2half2_rn(v1.z, v1.w);
    uint4 o;
    o.x = *(unsigned*)&h0; o.y = *(unsigned*)&h1;
    o.z = *(unsigned*)&h2; o.w = *(unsigned*)&h3;
    *(uint4*)(g_xh + m * K_DIM + k) = o;    // 16B aligned: j in {0,8}
}

// ---------------------------------------------------------------------------
// Kernel 1: fold per-8x8 DCT into conv weights (w' = D^T W D), fp16, [n][k].
// ---------------------------------------------------------------------------
__global__ void dct_weight_kernel(const float* __restrict__ w) {
    __shared__ float Ws[16][16];
    __shared__ float Ds[8][8];
    int o = blockIdx.x / CHAN, c = blockIdx.x % CHAN, tid = threadIdx.x;
    if (tid < 64) {
        int k = tid >> 3, n = tid & 7;
        double v = sqrt(2.0 / 8.0) * cos(PI_D * (2.0 * n + 1.0) * k / 16.0);
        if (k == 0) v *= (1.0 / sqrt(2.0));
        Ds[k][n] = (float)v;
    }
    Ws[tid >> 4][tid & 15] = w[(o * CHAN + c) * 256 + tid];
    __syncthreads();
    int i = tid >> 4, j = tid & 15;
    int bi = i & 8, bj = j & 8, ii = i & 7, jj = j & 7;
    float s = 0.0f;
    #pragma unroll
    for (int u = 0; u < 8; u++) {
        float du = Ds[u][ii];
        #pragma unroll
        for (int v = 0; v < 8; v++) s += du * Ws[bi + u][bj + v] * Ds[v][jj];
    }
    g_wt[(long)o * K_DIM + c * 256 + i * 16 + j] = __float2half_rn(s);
}

// ---------------------------------------------------------------------------
// Kernel 2: fp16 mma.sync m16n8k16 GEMM with ldmatrix fragment loads.
//   BM=128 BN=128 BK=32, 4-stage cp.async, 2 CTAs/SM, 8 warps (4m x 2n),
//   warp tile 32x64.  K-major fp16 smem, 80B row stride -> ldmatrix phases
//   hit byte offsets mod 128 {0,80,32,112,64,16,96,48}: conflict-free.
// ---------------------------------------------------------------------------
#define BM 128
#define BN 128
#define BK 32
#define STAGES 4
#define NT (K_DIM / BK)          // 24
#define ROWB 80                  // bytes per smem row (64 data + 16 pad)
#define TILE_B (BM * ROWB)       // 10240 bytes per operand tile
#define STG_B (2 * TILE_B)       // A then B : 20480
#define SMEM_BYTES (STAGES * STG_B)   // 81920

__global__ __launch_bounds__(256, 2)
void gemm_f16_kernel(const float* __restrict__ bias, float* __restrict__ out) {
    extern __shared__ __half smem[];
    const unsigned smem_b = (unsigned)__cvta_generic_to_shared(smem);
    const int tid  = threadIdx.x;
    const int lane = tid & 31, wid = tid >> 5;
    const int warp_m = wid >> 1, warp_n = wid & 1;
    const int g = lane >> 2, tig = lane & 3;

    const int m0 = blockIdx.y * BM;
    const int n0 = blockIdx.x * BN;

    // ---- global-load mapping: per operand 512 16B chunks, 2 per thread ----
    const int row0 = tid >> 2;      // rows row0, row0+64
    const int q    = tid & 3;       // 16B chunk within 64B k-row

    const __half* gA0 = g_xh + (long)(m0 + row0) * K_DIM + q * 8;
    const __half* gA1 = g_xh + (long)(m0 + row0 + 64) * K_DIM + q * 8;
    const __half* gB0 = g_wt + (long)(n0 + row0) * K_DIM + q * 8;
    const __half* gB1 = g_wt + (long)(n0 + row0 + 64) * K_DIM + q * 8;

    const unsigned stA0 = row0 * ROWB + q * 16;
    const unsigned stA1 = (row0 + 64) * ROWB + q * 16;

    auto load_tile = [&](int t, int slot) {
        const unsigned base = smem_b + slot * STG_B;
        const int k0 = t * BK;
        CP_ASYNC16(base + stA0, gA0 + k0);
        CP_ASYNC16(base + stA1, gA1 + k0);
        CP_ASYNC16(base + TILE_B + stA0, gB0 + k0);
        CP_ASYNC16(base + TILE_B + stA1, gB1 + k0);
    };

    // ---- ldmatrix per-thread address offsets (within a stage) ----
    const int lm_row = lane & 7;
    const int lm_hi  = (lane >> 3) & 1;    // +8 m rows for mats 1,3
    const int lm_k8  = (lane >> 4) * 8;    // +8 k cols for mats 2,3
    unsigned a_off[2];                     // per mt
    #pragma unroll
    for (int mt = 0; mt < 2; mt++)
        a_off[mt] = (warp_m * 32 + mt * 16 + lm_hi * 8 + lm_row) * ROWB + lm_k8 * 2;
    const int b_hi = (lane >> 3) & 1;      // +8 k cols for mats 1,3
    const int b_nt = (lane >> 4);          // second n-tile for mats 2,3
    unsigned b_off[4];                     // per g2
    #pragma unroll
    for (int g2 = 0; g2 < 4; g2++)
        b_off[g2] = TILE_B + (warp_n * 64 + (2 * g2 + b_nt) * 8 + lm_row) * ROWB
                  + b_hi * 16;

    float acc[2][8][4];
    #pragma unroll
    for (int i = 0; i < 2; i++)
        #pragma unroll
        for (int j = 0; j < 8; j++)
            #pragma unroll
            for (int p = 0; p < 4; p++) acc[i][j][p] = 0.0f;

    #pragma unroll
    for (int s = 0; s < STAGES - 1; s++) { load_tile(s, s); CP_COMMIT(); }

    auto compute_tile = [&](unsigned base) {
        #pragma unroll
        for (int kk = 0; kk < 2; kk++) {      // two k16 steps per BK=32
            unsigned afr[2][4];
            #pragma unroll
            for (int mt = 0; mt < 2; mt++)
                LDSM_X4(afr[mt][0], afr[mt][1], afr[mt][2], afr[mt][3],
                        base + a_off[mt] + kk * 32);
            unsigned bfr[8][2];
            #pragma unroll
            for (int g2 = 0; g2 < 4; g2++)
                LDSM_X4(bfr[2 * g2][0], bfr[2 * g2][1],
                        bfr[2 * g2 + 1][0], bfr[2 * g2 + 1][1],
                        base + b_off[g2] + kk * 32);
            #pragma unroll
            for (int mt = 0; mt < 2; mt++)
                #pragma unroll
                for (int nt = 0; nt < 8; nt++)
                    mma_f16(acc[mt][nt], afr[mt], bfr[nt]);
        }
    };

    // main loop: NT=24, unrolled by STAGES so slot offsets are compile-time
    for (int t0 = 0; t0 < NT; t0 += STAGES) {
        #pragma unroll
        for (int u = 0; u < STAGES; u++) {
            const int t = t0 + u;
            CP_WAIT(STAGES - 2);
            __syncthreads();
            const int tn = t + STAGES - 1;
            if (tn < NT) load_tile(tn, tn & (STAGES - 1));
            CP_COMMIT();
            compute_tile(smem_b + u * STG_B);
            __syncthreads();
        }
    }

    // ---- epilogue: bias + store ----
    #pragma unroll
    for (int mt = 0; mt < 2; mt++) {
        const int r0 = m0 + warp_m * 32 + mt * 16 + g;
        #pragma unroll
        for (int nt = 0; nt < 8; nt++) {
            const int col = n0 + warp_n * 64 + nt * 8 + 2 * tig;
            const float b0 = bias[col], b1 = bias[col + 1];
            float2 v0 = make_float2(acc[mt][nt][0] + b0, acc[mt][nt][1] + b1);
            float2 v1 = make_float2(acc[mt][nt][2] + b0, acc[mt][nt][3] + b1);
            *(float2*)(out + (long)r0 * N_DIM + col)       = v0;
            *(float2*)(out + (long)(r0 + 8) * N_DIM + col) = v1;
        }
    }
}

// ---------------------------------------------------------------------------
extern "C" void kernel_launch(void* const* d_in, const int* in_sizes, int n_in,
                              void* d_out, int out_size) {
    const float* x = (const float*)d_in[0];   // [128,3,224,224]
    const float* w = (const float*)d_in[1];   // [768,3,16,16]
    const float* b = (const float*)d_in[2];   // [768]
    float* out = (float*)d_out;               // [128,196,768]

    cudaFuncSetAttribute(gemm_f16_kernel,
                         cudaFuncAttributeMaxDynamicSharedMemorySize, SMEM_BYTES);

    const int NF8 = BATCH * CHAN * HW * HW / 8;   // 2,408,448
    im2col_h_kernel<<<NF8 / 256, 256>>>(x);
    dct_weight_kernel<<<N_DIM * CHAN, 256>>>(w);
    gemm_f16_kernel<<<dim3(N_DIM / BN, M_DIM / BM), 256, SMEM_BYTES>>>(b, out);
}

// round 11
// speedup vs baseline: 5.0388x; 1.0007x over previous
#include <cuda_runtime.h>
#include <cuda_fp16.h>
#include <math.h>
#include <stdint.h>

// ---------------- problem constants ----------------
#define BATCH   128
#define CHAN    3
#define HW      224
#define PATCH   16
#define NPD     14
#define NPATCH  (NPD*NPD)           // 196
#define M_DIM   (BATCH*NPATCH)      // 25088
#define K_DIM   (CHAN*PATCH*PATCH)  // 768
#define N_DIM   768

#define PI_D 3.141592653589793238462643383279502884

// fp16 scratch: DCT-folded weights [n][k]; im2col'd input [m][k]
__device__ __half g_wt[N_DIM * K_DIM];
__device__ __half g_xh[(long)M_DIM * K_DIM];

__device__ __forceinline__ void mma_f16(float* c, const unsigned* a, const unsigned* b) {
    asm volatile(
        "mma.sync.aligned.m16n8k16.row.col.f32.f16.f16.f32 "
        "{%0,%1,%2,%3}, {%4,%5,%6,%7}, {%8,%9}, {%0,%1,%2,%3};"
        : "+f"(c[0]), "+f"(c[1]), "+f"(c[2]), "+f"(c[3])
        : "r"(a[0]), "r"(a[1]), "r"(a[2]), "r"(a[3]), "r"(b[0]), "r"(b[1]));
}
#define LDSM_X4(r0, r1, r2, r3, addr) \
    asm volatile("ldmatrix.sync.aligned.m8n8.x4.shared.b16 {%0,%1,%2,%3}, [%4];" \
                 : "=r"(r0), "=r"(r1), "=r"(r2), "=r"(r3) : "r"(addr))
#define CP_ASYNC16(saddr, gptr) \
    asm volatile("cp.async.cg.shared.global [%0], [%1], 16;" :: "r"(saddr), "l"(gptr))
#define CP_COMMIT()  asm volatile("cp.async.commit_group;" ::: "memory")
#define CP_WAIT(n)   asm volatile("cp.async.wait_group %0;" :: "n"(n) : "memory")

// ---------------------------------------------------------------------------
// Kernel 0: im2col x (fp32 NCHW) -> g_xh (fp16, [m][k]).  8 floats per thread.
// ---------------------------------------------------------------------------
__global__ void im2col_h_kernel(const float* __restrict__ x) {
    int f = blockIdx.x * blockDim.x + threadIdx.x;      // 8-float chunk index
    const float4* xp = (const float4*)x + (long)f * 2;
    float4 v0 = xp[0], v1 = xp[1];
    int w8 = f % 28; int rest = f / 28;
    int h = rest % HW; rest /= HW;
    int c = rest % CHAN; int b = rest / CHAN;
    int j = (w8 * 8) & 15, pw = (w8 * 8) >> 4;
    int i = h & 15,        ph = h >> 4;
    long m = (long)b * NPATCH + ph * NPD + pw;
    int  k = c * 256 + i * 16 + j;
    __half2 h0 = __floats2half2_rn(v0.x, v0.y);
    __half2 h1 = __floats2half2_rn(v0.z, v0.w);
    __half2 h2 = __floats2half2_rn(v1.x, v1.y);
    __half2 h3 = __floats2half2_rn(v1.z, v1.w);
    uint4 o;
    o.x = *(unsigned*)&h0; o.y = *(unsigned*)&h1;
    o.z = *(unsigned*)&h2; o.w = *(unsigned*)&h3;
    *(uint4*)(g_xh + m * K_DIM + k) = o;    // 16B aligned: j in {0,8}
}

// ---------------------------------------------------------------------------
// Kernel 1: fold per-8x8 DCT into conv weights (w' = D^T W D), fp16, [n][k].
// ---------------------------------------------------------------------------
__global__ void dct_weight_kernel(const float* __restrict__ w) {
    __shared__ float Ws[16][16];
    __shared__ float Ds[8][8];
    int o = blockIdx.x / CHAN, c = blockIdx.x % CHAN, tid = threadIdx.x;
    if (tid < 64) {
        int k = tid >> 3, n = tid & 7;
        double v = sqrt(2.0 / 8.0) * cos(PI_D * (2.0 * n + 1.0) * k / 16.0);
        if (k == 0) v *= (1.0 / sqrt(2.0));
        Ds[k][n] = (float)v;
    }
    Ws[tid >> 4][tid & 15] = w[(o * CHAN + c) * 256 + tid];
    __syncthreads();
    int i = tid >> 4, j = tid & 15;
    int bi = i & 8, bj = j & 8, ii = i & 7, jj = j & 7;
    float s = 0.0f;
    #pragma unroll
    for (int u = 0; u < 8; u++) {
        float du = Ds[u][ii];
        #pragma unroll
        for (int v = 0; v < 8; v++) s += du * Ws[bi + u][bj + v] * Ds[v][jj];
    }
    g_wt[(long)o * K_DIM + c * 256 + i * 16 + j] = __float2half_rn(s);
}

// ---------------------------------------------------------------------------
// Kernel 2: fp16 mma.sync m16n8k16 GEMM, ldmatrix + intra-tile fragment
// pipelining, single __syncthreads per tile.
//   BM=128 BN=128 BK=32, 4-stage cp.async, 2 CTAs/SM, 8 warps (4m x 2n),
//   warp tile 32x64.  K-major fp16 smem, 80B row stride (conflict-free).
// ---------------------------------------------------------------------------
#define BM 128
#define BN 128
#define BK 32
#define STAGES 4
#define NT (K_DIM / BK)          // 24
#define ROWB 80                  // bytes per smem row (64 data + 16 pad)
#define TILE_B (BM * ROWB)       // 10240 bytes per operand tile
#define STG_B (2 * TILE_B)       // A then B : 20480
#define SMEM_BYTES (STAGES * STG_B)   // 81920

__global__ __launch_bounds__(256, 2)
void gemm_f16_kernel(const float* __restrict__ bias, float* __restrict__ out) {
    extern __shared__ __half smem[];
    const unsigned smem_b = (unsigned)__cvta_generic_to_shared(smem);
    const int tid  = threadIdx.x;
    const int lane = tid & 31, wid = tid >> 5;
    const int warp_m = wid >> 1, warp_n = wid & 1;
    const int g = lane >> 2, tig = lane & 3;

    const int m0 = blockIdx.y * BM;
    const int n0 = blockIdx.x * BN;

    // ---- global-load mapping: per operand 512 16B chunks, 2 per thread ----
    const int row0 = tid >> 2;      // rows row0, row0+64
    const int q    = tid & 3;       // 16B chunk within 64B k-row

    const __half* gA0 = g_xh + (long)(m0 + row0) * K_DIM + q * 8;
    const __half* gA1 = g_xh + (long)(m0 + row0 + 64) * K_DIM + q * 8;
    const __half* gB0 = g_wt + (long)(n0 + row0) * K_DIM + q * 8;
    const __half* gB1 = g_wt + (long)(n0 + row0 + 64) * K_DIM + q * 8;

    const unsigned stA0 = row0 * ROWB + q * 16;
    const unsigned stA1 = (row0 + 64) * ROWB + q * 16;

    auto load_tile = [&](int t, int slot) {
        const unsigned base = smem_b + slot * STG_B;
        const int k0 = t * BK;
        CP_ASYNC16(base + stA0, gA0 + k0);
        CP_ASYNC16(base + stA1, gA1 + k0);
        CP_ASYNC16(base + TILE_B + stA0, gB0 + k0);
        CP_ASYNC16(base + TILE_B + stA1, gB1 + k0);
    };

    // ---- ldmatrix per-thread address offsets (within a stage) ----
    const int lm_row = lane & 7;
    const int lm_hi  = (lane >> 3) & 1;    // +8 m rows for mats 1,3
    const int lm_k8  = (lane >> 4) * 8;    // +8 k cols for mats 2,3
    unsigned a_off[2];                     // per mt
    #pragma unroll
    for (int mt = 0; mt < 2; mt++)
        a_off[mt] = (warp_m * 32 + mt * 16 + lm_hi * 8 + lm_row) * ROWB + lm_k8 * 2;
    const int b_hi = (lane >> 3) & 1;      // +8 k cols for mats 1,3
    const int b_nt = (lane >> 4);          // second n-tile for mats 2,3
    unsigned b_off[4];                     // per g2
    #pragma unroll
    for (int g2 = 0; g2 < 4; g2++)
        b_off[g2] = TILE_B + (warp_n * 64 + (2 * g2 + b_nt) * 8 + lm_row) * ROWB
                  + b_hi * 16;

    float acc[2][8][4];
    #pragma unroll
    for (int i = 0; i < 2; i++)
        #pragma unroll
        for (int j = 0; j < 8; j++)
            #pragma unroll
            for (int p = 0; p < 4; p++) acc[i][j][p] = 0.0f;

    #pragma unroll
    for (int s = 0; s < STAGES - 1; s++) { load_tile(s, s); CP_COMMIT(); }

    // intra-tile pipelined compute: kk0 frags + A-kk1 up front, B-kk1 loads
    // overlap the kk0 MMA burst.
    auto compute_tile = [&](unsigned base) {
        unsigned a0[2][4], a1[2][4], b0f[8][2], b1f[8][2];
        #pragma unroll
        for (int mt = 0; mt < 2; mt++)
            LDSM_X4(a0[mt][0], a0[mt][1], a0[mt][2], a0[mt][3], base + a_off[mt]);
        #pragma unroll
        for (int g2 = 0; g2 < 4; g2++)
            LDSM_X4(b0f[2 * g2][0], b0f[2 * g2][1],
                    b0f[2 * g2 + 1][0], b0f[2 * g2 + 1][1], base + b_off[g2]);
        #pragma unroll
        for (int mt = 0; mt < 2; mt++)
            LDSM_X4(a1[mt][0], a1[mt][1], a1[mt][2], a1[mt][3],
                    base + a_off[mt] + 32);
        #pragma unroll
        for (int mt = 0; mt < 2; mt++)
            #pragma unroll
            for (int nt = 0; nt < 8; nt++)
                mma_f16(acc[mt][nt], a0[mt], b0f[nt]);
        #pragma unroll
        for (int g2 = 0; g2 < 4; g2++)
            LDSM_X4(b1f[2 * g2][0], b1f[2 * g2][1],
                    b1f[2 * g2 + 1][0], b1f[2 * g2 + 1][1],
                    base + b_off[g2] + 32);
        #pragma unroll
        for (int mt = 0; mt < 2; mt++)
            #pragma unroll
            for (int nt = 0; nt < 8; nt++)
                mma_f16(acc[mt][nt], a1[mt], b1f[nt]);
    };

    // main loop: single __syncthreads per tile.
    // Safety: iteration t's load targets slot (t+3)%4 == (t-1)%4; the leading
    // sync orders all warps past compute(t-1), so no reader remains.
    for (int t0 = 0; t0 < NT; t0 += STAGES) {
        #pragma unroll
        for (int u = 0; u < STAGES; u++) {
            const int t = t0 + u;
            CP_WAIT(STAGES - 2);
            __syncthreads();
            const int tn = t + STAGES - 1;
            if (tn < NT) load_tile(tn, tn & (STAGES - 1));
            CP_COMMIT();
            compute_tile(smem_b + u * STG_B);
        }
    }

    // ---- epilogue: bias + store ----
    #pragma unroll
    for (int mt = 0; mt < 2; mt++) {
        const int r0 = m0 + warp_m * 32 + mt * 16 + g;
        #pragma unroll
        for (int nt = 0; nt < 8; nt++) {
            const int col = n0 + warp_n * 64 + nt * 8 + 2 * tig;
            const float b0 = bias[col], b1 = bias[col + 1];
            float2 v0 = make_float2(acc[mt][nt][0] + b0, acc[mt][nt][1] + b1);
            float2 v1 = make_float2(acc[mt][nt][2] + b0, acc[mt][nt][3] + b1);
            *(float2*)(out + (long)r0 * N_DIM + col)       = v0;
            *(float2*)(out + (long)(r0 + 8) * N_DIM + col) = v1;
        }
    }
}

// ---------------------------------------------------------------------------
extern "C" void kernel_launch(void* const* d_in, const int* in_sizes, int n_in,
                              void* d_out, int out_size) {
    const float* x = (const float*)d_in[0];   // [128,3,224,224]
    const float* w = (const float*)d_in[1];   // [768,3,16,16]
    const float* b = (const float*)d_in[2];   // [768]
    float* out = (float*)d_out;               // [128,196,768]

    cudaFuncSetAttribute(gemm_f16_kernel,
                         cudaFuncAttributeMaxDynamicSharedMemorySize, SMEM_BYTES);

    const int NF8 = BATCH * CHAN * HW * HW / 8;   // 2,408,448
    im2col_h_kernel<<<NF8 / 256, 256>>>(x);
    dct_weight_kernel<<<N_DIM * CHAN, 256>>>(w);
    gemm_f16_kernel<<<dim3(N_DIM / BN, M_DIM / BM), 256, SMEM_BYTES>>>(b, out);
}